// round 6
// baseline (speedup 1.0000x reference)
#include <cuda_runtime.h>

#define N       8192
#define GRID_A  148            // 1 block per SM, one wave
#define BLK_A   512            // 16 warps, 16 cols/thread
#define NITER   10
#define LOG2E   1.4426950408889634f
#define QSCALE  (LOG2E * 2048.0f)    // x -> log2 units, 11 fractional bits
#define INVQ    (1.0f / 2048.0f)

// c and r are stored in LOG2 units (c*log2e, r*log2e)
__device__ float g_cl[N];
__device__ float g_rl[N];
__device__ float g_part[(size_t)GRID_A * N];
// quantized matrix: q[i,j] = round(x[i,j]*LOG2E*2048) as s16, packed 8/int4
__device__ int4  g_xq[(size_t)N * N / 8];

// ---------------------------------------------------------------------------
__global__ void init_c_kernel() {
    int i = blockIdx.x * blockDim.x + threadIdx.x;
    if (i < N) g_cl[i] = 0.0f;
}

// ---------------------------------------------------------------------------
// decode 8 s16 (log2-fixed-point, 11 frac bits) from an int4
// ---------------------------------------------------------------------------
__device__ __forceinline__ void dec8(const int4 q, float f[8]) {
    f[0] = (float)(short)(q.x & 0xffff);  f[1] = (float)(q.x >> 16);
    f[2] = (float)(short)(q.y & 0xffff);  f[3] = (float)(q.y >> 16);
    f[4] = (float)(short)(q.z & 0xffff);  f[5] = (float)(q.z >> 16);
    f[6] = (float)(short)(q.w & 0xffff);  f[7] = (float)(q.w >> 16);
}

__device__ __forceinline__ int pack2(int lo, int hi) {
    return (lo & 0xffff) | (hi << 16);
}

// ---------------------------------------------------------------------------
// Block-level row reduction helpers (double-buffered smem, ONE barrier/row).
// 16 warps; s_warp entries [16..31] read as zero via lane guard.
// ---------------------------------------------------------------------------

// ---------------------------------------------------------------------------
// Iteration 0 fused with quantization: c == 0, read fp32 X, emit q, and do
// the row pass (e computed FROM q so later passes are consistent).
// ---------------------------------------------------------------------------
__global__ void __launch_bounds__(BLK_A, 1)
row_pass_first_kernel(const float* __restrict__ X) {
    __shared__ float s_warp[2][32];

    const int tid  = threadIdx.x;
    const int lane = tid & 31;
    const int wid  = tid >> 5;
    const int b    = blockIdx.x;
    const int row0 = (int)(((long long)N * b)       / GRID_A);
    const int row1 = (int)(((long long)N * (b + 1)) / GRID_A);

    float acc[16];
#pragma unroll
    for (int k = 0; k < 16; k++) acc[k] = 0.0f;

    const float4* x4 = (const float4*)X;
    // preload first row: f4 indices 2*tid, 2*tid+1, 2*(tid+512), 2*(tid+512)+1
    float4 xc[4];
    {
        const size_t rb = (size_t)row0 * 2048;
        xc[0] = __ldg(x4 + rb + 2 * tid);
        xc[1] = __ldg(x4 + rb + 2 * tid + 1);
        xc[2] = __ldg(x4 + rb + 2 * (tid + 512));
        xc[3] = __ldg(x4 + rb + 2 * (tid + 512) + 1);
    }

    int buf = 0;
    for (int row = row0; row < row1; ++row, buf ^= 1) {
        // prefetch next row
        float4 xn[4];
        {
            const int nr = (row + 1 < row1) ? row + 1 : row;
            const size_t rb = (size_t)nr * 2048;
            xn[0] = __ldg(x4 + rb + 2 * tid);
            xn[1] = __ldg(x4 + rb + 2 * tid + 1);
            xn[2] = __ldg(x4 + rb + 2 * (tid + 512));
            xn[3] = __ldg(x4 + rb + 2 * (tid + 512) + 1);
        }

        // quantize + exp2(q/2048), row partial sum
        int qi[16];
        const float* xf = (const float*)xc;
        float e[16];
        float psum = 0.0f;
#pragma unroll
        for (int k = 0; k < 16; k++) {
            qi[k] = __float2int_rn(xf[k] * QSCALE);
            e[k]  = exp2f((float)qi[k] * INVQ);
            psum += e[k];
        }
        // store q (2 int4 per thread per row)
        {
            int4 o0, o1;
            o0.x = pack2(qi[0],  qi[1]);  o0.y = pack2(qi[2],  qi[3]);
            o0.z = pack2(qi[4],  qi[5]);  o0.w = pack2(qi[6],  qi[7]);
            o1.x = pack2(qi[8],  qi[9]);  o1.y = pack2(qi[10], qi[11]);
            o1.z = pack2(qi[12], qi[13]); o1.w = pack2(qi[14], qi[15]);
            g_xq[(size_t)row * 1024 + tid]       = o0;
            g_xq[(size_t)row * 1024 + tid + 512] = o1;
        }

        // warp reduce
#pragma unroll
        for (int off = 16; off > 0; off >>= 1)
            psum += __shfl_xor_sync(0xffffffffu, psum, off);
        if (lane == 0) s_warp[buf][wid] = psum;
        __syncthreads();

        float v = (lane < 16) ? s_warp[buf][lane] : 0.0f;
#pragma unroll
        for (int off = 16; off > 0; off >>= 1)
            v += __shfl_xor_sync(0xffffffffu, v, off);

        const float rcp = __fdividef(1.0f, v);
        if (tid == 0) g_rl[row] = __log2f(v);

#pragma unroll
        for (int k = 0; k < 16; k++) acc[k] = fmaf(e[k], rcp, acc[k]);

#pragma unroll
        for (int k = 0; k < 4; k++) xc[k] = xn[k];
    }

    float4* pp = (float4*)(g_part + (size_t)b * N);
    pp[2 * tid]               = make_float4(acc[0],  acc[1],  acc[2],  acc[3]);
    pp[2 * tid + 1]           = make_float4(acc[4],  acc[5],  acc[6],  acc[7]);
    pp[2 * (tid + 512)]       = make_float4(acc[8],  acc[9],  acc[10], acc[11]);
    pp[2 * (tid + 512) + 1]   = make_float4(acc[12], acc[13], acc[14], acc[15]);
}

// ---------------------------------------------------------------------------
// Steady-state row pass (iters 1..9): int16 input, software-pipelined so the
// next row's MUFU batch issues while the current row's block-reduce drains.
//   e_ij = exp2(q_ij/2048 - cl_j);  rl[i] = log2(sum_j e);  part += e/S
// ---------------------------------------------------------------------------
__global__ void __launch_bounds__(BLK_A, 1)
row_pass_kernel() {
    __shared__ float s_warp[2][32];

    const int tid  = threadIdx.x;
    const int lane = tid & 31;
    const int wid  = tid >> 5;
    const int b    = blockIdx.x;
    const int row0 = (int)(((long long)N * b)       / GRID_A);
    const int row1 = (int)(((long long)N * (b + 1)) / GRID_A);

    // column log2-offsets for this thread's 16 columns (registers)
    float cl[16];
    {
        const float4* c4 = (const float4*)g_cl;
        float4 c0 = __ldg(c4 + 2 * tid);
        float4 c1 = __ldg(c4 + 2 * tid + 1);
        float4 c2 = __ldg(c4 + 2 * (tid + 512));
        float4 c3 = __ldg(c4 + 2 * (tid + 512) + 1);
        cl[0]=c0.x; cl[1]=c0.y; cl[2]=c0.z; cl[3]=c0.w;
        cl[4]=c1.x; cl[5]=c1.y; cl[6]=c1.z; cl[7]=c1.w;
        cl[8]=c2.x; cl[9]=c2.y; cl[10]=c2.z; cl[11]=c2.w;
        cl[12]=c3.x; cl[13]=c3.y; cl[14]=c3.z; cl[15]=c3.w;
    }

    float acc[16];
#pragma unroll
    for (int k = 0; k < 16; k++) acc[k] = 0.0f;

    // 3-deep row prefetch (each row = 2 int4 per thread)
    int4 qa[2], qb[2], qc[2];
    {
        const int r1 = (row0 + 1 < row1) ? row0 + 1 : row1 - 1;
        const int r2 = (row0 + 2 < row1) ? row0 + 2 : row1 - 1;
        qa[0] = g_xq[(size_t)row0 * 1024 + tid];
        qa[1] = g_xq[(size_t)row0 * 1024 + tid + 512];
        qb[0] = g_xq[(size_t)r1   * 1024 + tid];
        qb[1] = g_xq[(size_t)r1   * 1024 + tid + 512];
        qc[0] = g_xq[(size_t)r2   * 1024 + tid];
        qc[1] = g_xq[(size_t)r2   * 1024 + tid + 512];
    }

    // prologue: e for row0
    float e_cur[16], psum_cur;
    {
        float f[16];
        dec8(qa[0], f); dec8(qa[1], f + 8);
        psum_cur = 0.0f;
#pragma unroll
        for (int k = 0; k < 16; k++) {
            e_cur[k] = exp2f(fmaf(f[k], INVQ, -cl[k]));
            psum_cur += e_cur[k];
        }
    }

    int buf = 0;
    for (int row = row0; row < row1; ++row, buf ^= 1) {
        // ---- publish this row's warp partial ----
        float p = psum_cur;
#pragma unroll
        for (int off = 16; off > 0; off >>= 1)
            p += __shfl_xor_sync(0xffffffffu, p, off);
        if (lane == 0) s_warp[buf][wid] = p;
        __syncthreads();

        // ---- prefetch row+3 ----
        int4 qn[2];
        {
            const int pr = (row + 3 < row1) ? row + 3 : row1 - 1;
            qn[0] = g_xq[(size_t)pr * 1024 + tid];
            qn[1] = g_xq[(size_t)pr * 1024 + tid + 512];
        }

        // ---- compute e for row+1 (MUFU batch hides the reduce below) ----
        float e_nxt[16], psum_nxt = 0.0f;
        if (row + 1 < row1) {
            float f[16];
            dec8(qb[0], f); dec8(qb[1], f + 8);
#pragma unroll
            for (int k = 0; k < 16; k++) {
                e_nxt[k] = exp2f(fmaf(f[k], INVQ, -cl[k]));
                psum_nxt += e_nxt[k];
            }
        }

        // ---- second-level reduce for current row ----
        float v = (lane < 16) ? s_warp[buf][lane] : 0.0f;
#pragma unroll
        for (int off = 16; off > 0; off >>= 1)
            v += __shfl_xor_sync(0xffffffffu, v, off);

        const float rcp = __fdividef(1.0f, v);
        if (tid == 0) g_rl[row] = __log2f(v);

#pragma unroll
        for (int k = 0; k < 16; k++) acc[k] = fmaf(e_cur[k], rcp, acc[k]);

        // ---- rotate pipeline ----
#pragma unroll
        for (int k = 0; k < 16; k++) e_cur[k] = e_nxt[k];
        psum_cur = psum_nxt;
        qb[0] = qc[0]; qb[1] = qc[1];
        qc[0] = qn[0]; qc[1] = qn[1];
    }

    float4* pp = (float4*)(g_part + (size_t)b * N);
    pp[2 * tid]               = make_float4(acc[0],  acc[1],  acc[2],  acc[3]);
    pp[2 * tid + 1]           = make_float4(acc[4],  acc[5],  acc[6],  acc[7]);
    pp[2 * (tid + 512)]       = make_float4(acc[8],  acc[9],  acc[10], acc[11]);
    pp[2 * (tid + 512) + 1]   = make_float4(acc[12], acc[13], acc[14], acc[15]);
}

// ---------------------------------------------------------------------------
// Column reduce: cl[j] += log2( sum_b part[b][j] ).
// 256 blocks x 256 threads: 32 cols x 8 p-groups, coalesced, 4-way MLP.
// ---------------------------------------------------------------------------
__global__ void __launch_bounds__(256)
col_reduce_kernel() {
    __shared__ float s[8][32];
    const int jl = threadIdx.x & 31;
    const int pg = threadIdx.x >> 5;
    const int j  = blockIdx.x * 32 + jl;

    const int b0 = (GRID_A * pg)     / 8;
    const int b1 = (GRID_A * (pg+1)) / 8;

    const float* base = g_part + j;
    float a0 = 0.f, a1 = 0.f, a2 = 0.f, a3 = 0.f;
    int u = b0;
    for (; u + 4 <= b1; u += 4) {
        a0 += base[(size_t)(u + 0) * N];
        a1 += base[(size_t)(u + 1) * N];
        a2 += base[(size_t)(u + 2) * N];
        a3 += base[(size_t)(u + 3) * N];
    }
    for (; u < b1; ++u) a0 += base[(size_t)u * N];
    s[pg][jl] = (a0 + a1) + (a2 + a3);
    __syncthreads();

    if (pg == 0) {
        float t = 0.0f;
#pragma unroll
        for (int q = 0; q < 8; q++) t += s[q][jl];
        g_cl[j] += __log2f(t);
    }
}

// ---------------------------------------------------------------------------
// Final: out[i,j] = exp2(q[i,j]/2048 - rl[i] - cl[j]); 8 elems/thread.
// ---------------------------------------------------------------------------
__global__ void __launch_bounds__(256)
final_kernel(float* __restrict__ out) {
    const size_t idx = (size_t)blockIdx.x * blockDim.x + threadIdx.x; // int4 idx
    const int    row = (int)(idx >> 10);        // 1024 int4 per row
    const int    cg  = (int)(idx & 1023);

    const float nrl = -__ldg(g_rl + row);
    const float4* c4 = (const float4*)g_cl;
    float4 c0 = __ldg(c4 + 2 * cg);
    float4 c1 = __ldg(c4 + 2 * cg + 1);

    int4 q = g_xq[idx];
    float f[8];
    dec8(q, f);

    float4 o0, o1;
    o0.x = exp2f(fmaf(f[0], INVQ, nrl - c0.x));
    o0.y = exp2f(fmaf(f[1], INVQ, nrl - c0.y));
    o0.z = exp2f(fmaf(f[2], INVQ, nrl - c0.z));
    o0.w = exp2f(fmaf(f[3], INVQ, nrl - c0.w));
    o1.x = exp2f(fmaf(f[4], INVQ, nrl - c1.x));
    o1.y = exp2f(fmaf(f[5], INVQ, nrl - c1.y));
    o1.z = exp2f(fmaf(f[6], INVQ, nrl - c1.z));
    o1.w = exp2f(fmaf(f[7], INVQ, nrl - c1.w));

    float4* o4 = (float4*)out;
    o4[2 * idx]     = o0;
    o4[2 * idx + 1] = o1;
}

// ---------------------------------------------------------------------------
extern "C" void kernel_launch(void* const* d_in, const int* in_sizes, int n_in,
                              void* d_out, int out_size) {
    const float* X   = (const float*)d_in[0];
    float*       out = (float*)d_out;
    (void)in_sizes; (void)n_in; (void)out_size;

    init_c_kernel<<<N / 256, 256>>>();
    row_pass_first_kernel<<<GRID_A, BLK_A>>>(X);   // iter 0 + quantize
    col_reduce_kernel<<<N / 32, 256>>>();
    for (int it = 1; it < NITER; ++it) {
        row_pass_kernel<<<GRID_A, BLK_A>>>();
        col_reduce_kernel<<<N / 32, 256>>>();
    }
    final_kernel<<<(size_t)N * N / 8 / 256, 256>>>(out);
}

// round 7
// speedup vs baseline: 1.2190x; 1.2190x over previous
#include <cuda_runtime.h>
#include <cuda_fp16.h>

#define N       8192
#define GRID_A  148            // 1 block per SM, one wave
#define BLK_A   1024           // 32 warps, 8 cols/thread
#define NITER   10
#define LOG2E   1.4426950408889634f

// Multiplicative column scale d_j = exp(-c_j); row inverse sums rinv_i = 1/S_i.
__device__ float  g_d[N];
__device__ float  g_rinv[N];
__device__ float  g_part[(size_t)GRID_A * N];
// E_ij = exp(x_ij) stored as fp16, packed 8 per int4.
__device__ int4   g_E[(size_t)N * N / 8];

// ---------------------------------------------------------------------------
__global__ void init_d_kernel() {
    int i = blockIdx.x * blockDim.x + threadIdx.x;
    if (i < N) g_d[i] = 1.0f;
}

// ---------------------------------------------------------------------------
// decode 8 fp16 from an int4 into fp32
// ---------------------------------------------------------------------------
__device__ __forceinline__ void dec8h(const int4 q, float f[8]) {
    float2 a;
    a = __half22float2(*(const __half2*)&q.x); f[0] = a.x; f[1] = a.y;
    a = __half22float2(*(const __half2*)&q.y); f[2] = a.x; f[3] = a.y;
    a = __half22float2(*(const __half2*)&q.z); f[4] = a.x; f[5] = a.y;
    a = __half22float2(*(const __half2*)&q.w); f[6] = a.x; f[7] = a.y;
}

__device__ __forceinline__ int packh2(float a, float b) {
    __half2 h = __floats2half2_rn(a, b);
    return *(const int*)&h;
}

// ---------------------------------------------------------------------------
// Iteration 0 fused with E-precompute: d == 1. Read fp32 X, write E=exp(x)
// as fp16, and do iter-0's row pass (e computed FROM the rounded fp16 so all
// later iterations are self-consistent).
// ---------------------------------------------------------------------------
__global__ void __launch_bounds__(BLK_A, 1)
row_pass_first_kernel(const float* __restrict__ X) {
    __shared__ float s_warp[2][32];

    const int tid  = threadIdx.x;
    const int lane = tid & 31;
    const int wid  = tid >> 5;
    const int b    = blockIdx.x;
    const int row0 = (int)(((long long)N * b)       / GRID_A);
    const int row1 = (int)(((long long)N * (b + 1)) / GRID_A);

    float acc[8];
#pragma unroll
    for (int k = 0; k < 8; k++) acc[k] = 0.0f;

    const float4* x4 = (const float4*)X;
    // preload first row (8 fp32 = 2 float4 per thread)
    float4 xc[2];
    {
        const size_t rb = (size_t)row0 * 2048;
        xc[0] = __ldg(x4 + rb + 2 * tid);
        xc[1] = __ldg(x4 + rb + 2 * tid + 1);
    }

    int buf = 0;
    for (int row = row0; row < row1; ++row, buf ^= 1) {
        // prefetch next row
        float4 xn[2];
        {
            const int nr = (row + 1 < row1) ? row + 1 : row;
            const size_t rb = (size_t)nr * 2048;
            xn[0] = __ldg(x4 + rb + 2 * tid);
            xn[1] = __ldg(x4 + rb + 2 * tid + 1);
        }

        // E = exp(x) -> fp16; e = fp32(E16); row partial sum
        const float* xf = (const float*)xc;
        float E32[8];
#pragma unroll
        for (int k = 0; k < 8; k++) E32[k] = exp2f(xf[k] * LOG2E);

        int4 o;
        o.x = packh2(E32[0], E32[1]);
        o.y = packh2(E32[2], E32[3]);
        o.z = packh2(E32[4], E32[5]);
        o.w = packh2(E32[6], E32[7]);
        g_E[(size_t)row * 1024 + tid] = o;

        float e[8];
        dec8h(o, e);   // rounded values, consistent with later iterations
        float psum = ((e[0] + e[1]) + (e[2] + e[3])) + ((e[4] + e[5]) + (e[6] + e[7]));

        // warp reduce
#pragma unroll
        for (int off = 16; off > 0; off >>= 1)
            psum += __shfl_xor_sync(0xffffffffu, psum, off);
        if (lane == 0) s_warp[buf][wid] = psum;
        __syncthreads();

        float v = s_warp[buf][lane];
#pragma unroll
        for (int off = 16; off > 0; off >>= 1)
            v += __shfl_xor_sync(0xffffffffu, v, off);

        const float rcp = __fdividef(1.0f, v);
        if (tid == 0) g_rinv[row] = rcp;

#pragma unroll
        for (int k = 0; k < 8; k++) acc[k] = fmaf(e[k], rcp, acc[k]);

        xc[0] = xn[0]; xc[1] = xn[1];
    }

    float4* pp = (float4*)(g_part + (size_t)b * N);
    pp[2 * tid]     = make_float4(acc[0], acc[1], acc[2], acc[3]);
    pp[2 * tid + 1] = make_float4(acc[4], acc[5], acc[6], acc[7]);
}

// ---------------------------------------------------------------------------
// Steady-state row pass (iters 1..9): NO transcendentals.
//   e_ij = E_ij * d_j ;  S_i = sum_j e ;  rinv_i = 1/S_i ;  part += e * rinv
// 1024 threads x 8 cols/thread = one int4 (8 fp16) load per thread per row.
// ---------------------------------------------------------------------------
__global__ void __launch_bounds__(BLK_A, 1)
row_pass_kernel() {
    __shared__ float s_warp[2][32];

    const int tid  = threadIdx.x;
    const int lane = tid & 31;
    const int wid  = tid >> 5;
    const int b    = blockIdx.x;
    const int row0 = (int)(((long long)N * b)       / GRID_A);
    const int row1 = (int)(((long long)N * (b + 1)) / GRID_A);

    // column scales d_j for this thread's 8 columns (registers)
    float d[8];
    {
        const float4* d4 = (const float4*)g_d;
        float4 d0 = __ldg(d4 + 2 * tid);
        float4 d1 = __ldg(d4 + 2 * tid + 1);
        d[0]=d0.x; d[1]=d0.y; d[2]=d0.z; d[3]=d0.w;
        d[4]=d1.x; d[5]=d1.y; d[6]=d1.z; d[7]=d1.w;
    }

    float acc[8];
#pragma unroll
    for (int k = 0; k < 8; k++) acc[k] = 0.0f;

    // 2-deep row prefetch (one int4 per thread per row)
    int4 q0 = __ldg(&g_E[(size_t)row0 * 1024 + tid]);
    int4 q1 = __ldg(&g_E[(size_t)min(row0 + 1, row1 - 1) * 1024 + tid]);

    int buf = 0;
    for (int row = row0; row < row1; ++row, buf ^= 1) {
        // prefetch row+2
        const int pr = (row + 2 < row1) ? row + 2 : row1 - 1;
        int4 qn = __ldg(&g_E[(size_t)pr * 1024 + tid]);

        // e = E * d, row partial sum
        float f[8];
        dec8h(q0, f);
        float e[8];
#pragma unroll
        for (int k = 0; k < 8; k++) e[k] = f[k] * d[k];
        float psum = ((e[0] + e[1]) + (e[2] + e[3])) + ((e[4] + e[5]) + (e[6] + e[7]));

        // warp reduce
#pragma unroll
        for (int off = 16; off > 0; off >>= 1)
            psum += __shfl_xor_sync(0xffffffffu, psum, off);
        if (lane == 0) s_warp[buf][wid] = psum;
        __syncthreads();

        // second level: every warp reduces all 32 partials (no 2nd barrier)
        float v = s_warp[buf][lane];
#pragma unroll
        for (int off = 16; off > 0; off >>= 1)
            v += __shfl_xor_sync(0xffffffffu, v, off);

        const float rcp = __fdividef(1.0f, v);
        if (tid == 0) g_rinv[row] = rcp;

#pragma unroll
        for (int k = 0; k < 8; k++) acc[k] = fmaf(e[k], rcp, acc[k]);

        q0 = q1; q1 = qn;
    }

    float4* pp = (float4*)(g_part + (size_t)b * N);
    pp[2 * tid]     = make_float4(acc[0], acc[1], acc[2], acc[3]);
    pp[2 * tid + 1] = make_float4(acc[4], acc[5], acc[6], acc[7]);
}

// ---------------------------------------------------------------------------
// Column reduce: t_j = sum_b part[b][j];  d_j /= t_j   (no logs needed)
// 256 blocks x 256 threads: 32 cols x 8 p-groups, coalesced, 4-way MLP.
// ---------------------------------------------------------------------------
__global__ void __launch_bounds__(256)
col_reduce_kernel() {
    __shared__ float s[8][32];
    const int jl = threadIdx.x & 31;
    const int pg = threadIdx.x >> 5;
    const int j  = blockIdx.x * 32 + jl;

    const int b0 = (GRID_A * pg)       / 8;
    const int b1 = (GRID_A * (pg + 1)) / 8;

    const float* base = g_part + j;
    float a0 = 0.f, a1 = 0.f, a2 = 0.f, a3 = 0.f;
    int u = b0;
    for (; u + 4 <= b1; u += 4) {
        a0 += base[(size_t)(u + 0) * N];
        a1 += base[(size_t)(u + 1) * N];
        a2 += base[(size_t)(u + 2) * N];
        a3 += base[(size_t)(u + 3) * N];
    }
    for (; u < b1; ++u) a0 += base[(size_t)u * N];
    s[pg][jl] = (a0 + a1) + (a2 + a3);
    __syncthreads();

    if (pg == 0) {
        float t = 0.0f;
#pragma unroll
        for (int q = 0; q < 8; q++) t += s[q][jl];
        g_d[j] = __fdividef(g_d[j], t);
    }
}

// ---------------------------------------------------------------------------
// Final: out[i,j] = E_ij * d_j * rinv_i  (pure multiplies)
// ---------------------------------------------------------------------------
__global__ void __launch_bounds__(256)
final_kernel(float* __restrict__ out) {
    const size_t idx = (size_t)blockIdx.x * blockDim.x + threadIdx.x; // int4 idx
    const int    row = (int)(idx >> 10);        // 1024 int4 per row
    const int    cg  = (int)(idx & 1023);

    const float ri = __ldg(g_rinv + row);
    const float4* d4 = (const float4*)g_d;
    float4 d0 = __ldg(d4 + 2 * cg);
    float4 d1 = __ldg(d4 + 2 * cg + 1);

    int4 q = __ldg(&g_E[idx]);
    float f[8];
    dec8h(q, f);

    float4 o0, o1;
    o0.x = f[0] * (d0.x * ri);
    o0.y = f[1] * (d0.y * ri);
    o0.z = f[2] * (d0.z * ri);
    o0.w = f[3] * (d0.w * ri);
    o1.x = f[4] * (d1.x * ri);
    o1.y = f[5] * (d1.y * ri);
    o1.z = f[6] * (d1.z * ri);
    o1.w = f[7] * (d1.w * ri);

    float4* o4 = (float4*)out;
    o4[2 * idx]     = o0;
    o4[2 * idx + 1] = o1;
}

// ---------------------------------------------------------------------------
extern "C" void kernel_launch(void* const* d_in, const int* in_sizes, int n_in,
                              void* d_out, int out_size) {
    const float* X   = (const float*)d_in[0];
    float*       out = (float*)d_out;
    (void)in_sizes; (void)n_in; (void)out_size;

    init_d_kernel<<<N / 256, 256>>>();
    row_pass_first_kernel<<<GRID_A, BLK_A>>>(X);   // iter 0 + E precompute
    col_reduce_kernel<<<N / 32, 256>>>();
    for (int it = 1; it < NITER; ++it) {
        row_pass_kernel<<<GRID_A, BLK_A>>>();
        col_reduce_kernel<<<N / 32, 256>>>();
    }
    final_kernel<<<(size_t)N * N / 8 / 256, 256>>>(out);
}

// round 8
// speedup vs baseline: 1.2249x; 1.0048x over previous
#include <cuda_runtime.h>
#include <cuda_fp16.h>

#define N       8192
#define GRID_A  148            // 1 block per SM, one wave
#define BLK_A   1024           // 32 warps, 8 cols/thread
#define NITER   10
#define LOG2E   1.4426950408889634f

// Multiplicative column scale d_j = exp(-c_j); row inverse sums rinv_i = 1/S_i.
__device__ float  g_d[N];
__device__ float  g_rinv[N];
__device__ float  g_part[(size_t)GRID_A * N];
// E_ij = exp(x_ij) stored as fp16, packed 8 per int4.
__device__ int4   g_E[(size_t)N * N / 8];

// ---------------------------------------------------------------------------
__global__ void init_d_kernel() {
    int i = blockIdx.x * blockDim.x + threadIdx.x;
    if (i < N) g_d[i] = 1.0f;
}

// ---------------------------------------------------------------------------
// decode 8 fp16 from an int4 into fp32
// ---------------------------------------------------------------------------
__device__ __forceinline__ void dec8h(const int4 q, float f[8]) {
    float2 a;
    a = __half22float2(*(const __half2*)&q.x); f[0] = a.x; f[1] = a.y;
    a = __half22float2(*(const __half2*)&q.y); f[2] = a.x; f[3] = a.y;
    a = __half22float2(*(const __half2*)&q.z); f[4] = a.x; f[5] = a.y;
    a = __half22float2(*(const __half2*)&q.w); f[6] = a.x; f[7] = a.y;
}

__device__ __forceinline__ int packh2(float a, float b) {
    __half2 h = __floats2half2_rn(a, b);
    return *(const int*)&h;
}

// ---------------------------------------------------------------------------
// Iteration 0 fused with E-precompute: d == 1. Read fp32 X, write E=exp(x)
// as fp16, and do iter-0's row pass (e computed FROM the rounded fp16 so all
// later iterations are self-consistent).
// ---------------------------------------------------------------------------
__global__ void __launch_bounds__(BLK_A, 1)
row_pass_first_kernel(const float* __restrict__ X) {
    __shared__ float s_warp[2][32];

    const int tid  = threadIdx.x;
    const int lane = tid & 31;
    const int wid  = tid >> 5;
    const int b    = blockIdx.x;
    const int row0 = (int)(((long long)N * b)       / GRID_A);
    const int row1 = (int)(((long long)N * (b + 1)) / GRID_A);

    float acc[8];
#pragma unroll
    for (int k = 0; k < 8; k++) acc[k] = 0.0f;

    const float4* x4 = (const float4*)X;
    // preload first row (8 fp32 = 2 float4 per thread)
    float4 xc[2];
    {
        const size_t rb = (size_t)row0 * 2048;
        xc[0] = __ldg(x4 + rb + 2 * tid);
        xc[1] = __ldg(x4 + rb + 2 * tid + 1);
    }

    int buf = 0;
    for (int row = row0; row < row1; ++row, buf ^= 1) {
        // prefetch next row
        float4 xn[2];
        {
            const int nr = (row + 1 < row1) ? row + 1 : row;
            const size_t rb = (size_t)nr * 2048;
            xn[0] = __ldg(x4 + rb + 2 * tid);
            xn[1] = __ldg(x4 + rb + 2 * tid + 1);
        }

        // E = exp(x) -> fp16; e = fp32(E16); row partial sum
        const float* xf = (const float*)xc;
        float E32[8];
#pragma unroll
        for (int k = 0; k < 8; k++) E32[k] = exp2f(xf[k] * LOG2E);

        int4 o;
        o.x = packh2(E32[0], E32[1]);
        o.y = packh2(E32[2], E32[3]);
        o.z = packh2(E32[4], E32[5]);
        o.w = packh2(E32[6], E32[7]);
        g_E[(size_t)row * 1024 + tid] = o;

        float e[8];
        dec8h(o, e);   // rounded values, consistent with later iterations
        float psum = ((e[0] + e[1]) + (e[2] + e[3])) + ((e[4] + e[5]) + (e[6] + e[7]));

        // warp reduce
#pragma unroll
        for (int off = 16; off > 0; off >>= 1)
            psum += __shfl_xor_sync(0xffffffffu, psum, off);
        if (lane == 0) s_warp[buf][wid] = psum;
        __syncthreads();

        float v = s_warp[buf][lane];
#pragma unroll
        for (int off = 16; off > 0; off >>= 1)
            v += __shfl_xor_sync(0xffffffffu, v, off);

        const float rcp = __fdividef(1.0f, v);
        if (tid == 0) g_rinv[row] = rcp;

#pragma unroll
        for (int k = 0; k < 8; k++) acc[k] = fmaf(e[k], rcp, acc[k]);

        xc[0] = xn[0]; xc[1] = xn[1];
    }

    float4* pp = (float4*)(g_part + (size_t)b * N);
    pp[2 * tid]     = make_float4(acc[0], acc[1], acc[2], acc[3]);
    pp[2 * tid + 1] = make_float4(acc[4], acc[5], acc[6], acc[7]);
}

// ---------------------------------------------------------------------------
// Steady-state row pass (iters 1..9): NO transcendentals.
//   e_ij = E_ij * d_j ;  S_i = sum_j e ;  rinv_i = 1/S_i ;  part += e * rinv
// 1024 threads x 8 cols/thread = one int4 (8 fp16) load per thread per row.
// ---------------------------------------------------------------------------
__global__ void __launch_bounds__(BLK_A, 1)
row_pass_kernel() {
    __shared__ float s_warp[2][32];

    const int tid  = threadIdx.x;
    const int lane = tid & 31;
    const int wid  = tid >> 5;
    const int b    = blockIdx.x;
    const int row0 = (int)(((long long)N * b)       / GRID_A);
    const int row1 = (int)(((long long)N * (b + 1)) / GRID_A);

    // column scales d_j for this thread's 8 columns (registers)
    float d[8];
    {
        const float4* d4 = (const float4*)g_d;
        float4 d0 = __ldg(d4 + 2 * tid);
        float4 d1 = __ldg(d4 + 2 * tid + 1);
        d[0]=d0.x; d[1]=d0.y; d[2]=d0.z; d[3]=d0.w;
        d[4]=d1.x; d[5]=d1.y; d[6]=d1.z; d[7]=d1.w;
    }

    float acc[8];
#pragma unroll
    for (int k = 0; k < 8; k++) acc[k] = 0.0f;

    // 2-deep row prefetch (one int4 per thread per row)
    int4 q0 = __ldg(&g_E[(size_t)row0 * 1024 + tid]);
    int4 q1 = __ldg(&g_E[(size_t)min(row0 + 1, row1 - 1) * 1024 + tid]);

    int buf = 0;
    for (int row = row0; row < row1; ++row, buf ^= 1) {
        // prefetch row+2
        const int pr = (row + 2 < row1) ? row + 2 : row1 - 1;
        int4 qn = __ldg(&g_E[(size_t)pr * 1024 + tid]);

        // e = E * d, row partial sum
        float f[8];
        dec8h(q0, f);
        float e[8];
#pragma unroll
        for (int k = 0; k < 8; k++) e[k] = f[k] * d[k];
        float psum = ((e[0] + e[1]) + (e[2] + e[3])) + ((e[4] + e[5]) + (e[6] + e[7]));

        // warp reduce
#pragma unroll
        for (int off = 16; off > 0; off >>= 1)
            psum += __shfl_xor_sync(0xffffffffu, psum, off);
        if (lane == 0) s_warp[buf][wid] = psum;
        __syncthreads();

        // second level: every warp reduces all 32 partials (no 2nd barrier)
        float v = s_warp[buf][lane];
#pragma unroll
        for (int off = 16; off > 0; off >>= 1)
            v += __shfl_xor_sync(0xffffffffu, v, off);

        const float rcp = __fdividef(1.0f, v);
        if (tid == 0) g_rinv[row] = rcp;

#pragma unroll
        for (int k = 0; k < 8; k++) acc[k] = fmaf(e[k], rcp, acc[k]);

        q0 = q1; q1 = qn;
    }

    float4* pp = (float4*)(g_part + (size_t)b * N);
    pp[2 * tid]     = make_float4(acc[0], acc[1], acc[2], acc[3]);
    pp[2 * tid + 1] = make_float4(acc[4], acc[5], acc[6], acc[7]);
}

// ---------------------------------------------------------------------------
// Column reduce: t_j = sum_b part[b][j];  d_j /= t_j   (no logs needed)
// 256 blocks x 256 threads: 32 cols x 8 p-groups, coalesced, 4-way MLP.
// ---------------------------------------------------------------------------
__global__ void __launch_bounds__(256)
col_reduce_kernel() {
    __shared__ float s[8][32];
    const int jl = threadIdx.x & 31;
    const int pg = threadIdx.x >> 5;
    const int j  = blockIdx.x * 32 + jl;

    const int b0 = (GRID_A * pg)       / 8;
    const int b1 = (GRID_A * (pg + 1)) / 8;

    const float* base = g_part + j;
    float a0 = 0.f, a1 = 0.f, a2 = 0.f, a3 = 0.f;
    int u = b0;
    for (; u + 4 <= b1; u += 4) {
        a0 += base[(size_t)(u + 0) * N];
        a1 += base[(size_t)(u + 1) * N];
        a2 += base[(size_t)(u + 2) * N];
        a3 += base[(size_t)(u + 3) * N];
    }
    for (; u < b1; ++u) a0 += base[(size_t)u * N];
    s[pg][jl] = (a0 + a1) + (a2 + a3);
    __syncthreads();

    if (pg == 0) {
        float t = 0.0f;
#pragma unroll
        for (int q = 0; q < 8; q++) t += s[q][jl];
        g_d[j] = __fdividef(g_d[j], t);
    }
}

// ---------------------------------------------------------------------------
// Final: out[i,j] = E_ij * d_j * rinv_i  (pure multiplies)
// ---------------------------------------------------------------------------
__global__ void __launch_bounds__(256)
final_kernel(float* __restrict__ out) {
    const size_t idx = (size_t)blockIdx.x * blockDim.x + threadIdx.x; // int4 idx
    const int    row = (int)(idx >> 10);        // 1024 int4 per row
    const int    cg  = (int)(idx & 1023);

    const float ri = __ldg(g_rinv + row);
    const float4* d4 = (const float4*)g_d;
    float4 d0 = __ldg(d4 + 2 * cg);
    float4 d1 = __ldg(d4 + 2 * cg + 1);

    int4 q = __ldg(&g_E[idx]);
    float f[8];
    dec8h(q, f);

    float4 o0, o1;
    o0.x = f[0] * (d0.x * ri);
    o0.y = f[1] * (d0.y * ri);
    o0.z = f[2] * (d0.z * ri);
    o0.w = f[3] * (d0.w * ri);
    o1.x = f[4] * (d1.x * ri);
    o1.y = f[5] * (d1.y * ri);
    o1.z = f[6] * (d1.z * ri);
    o1.w = f[7] * (d1.w * ri);

    float4* o4 = (float4*)out;
    o4[2 * idx]     = o0;
    o4[2 * idx + 1] = o1;
}

// ---------------------------------------------------------------------------
extern "C" void kernel_launch(void* const* d_in, const int* in_sizes, int n_in,
                              void* d_out, int out_size) {
    const float* X   = (const float*)d_in[0];
    float*       out = (float*)d_out;
    (void)in_sizes; (void)n_in; (void)out_size;

    init_d_kernel<<<N / 256, 256>>>();
    row_pass_first_kernel<<<GRID_A, BLK_A>>>(X);   // iter 0 + E precompute
    col_reduce_kernel<<<N / 32, 256>>>();
    for (int it = 1; it < NITER; ++it) {
        row_pass_kernel<<<GRID_A, BLK_A>>>();
        col_reduce_kernel<<<N / 32, 256>>>();
    }
    final_kernel<<<(size_t)N * N / 8 / 256, 256>>>(out);
}

// round 9
// speedup vs baseline: 1.2278x; 1.0024x over previous
#include <cuda_runtime.h>
#include <cuda_fp16.h>

#define N       8192
#define GRID_A  148            // 1 block per SM, one wave
#define BLK_A   1024           // 32 warps, 8 cols/thread
#define NITER   10
#define LOG2E   1.4426950408889634f

// Multiplicative column scale d_j = exp(-c_j); row inverse sums rinv_i = 1/S_i.
__device__ float  g_d[N];
__device__ float  g_rinv[N];
__device__ float  g_part[(size_t)GRID_A * N];
// E_ij = exp(x_ij) stored as fp16, packed 8 per int4.
__device__ int4   g_E[(size_t)N * N / 8];

// ---------------------------------------------------------------------------
__global__ void init_d_kernel() {
    int i = blockIdx.x * blockDim.x + threadIdx.x;
    if (i < N) g_d[i] = 1.0f;
}

// ---------------------------------------------------------------------------
// decode 8 fp16 from an int4 into fp32
// ---------------------------------------------------------------------------
__device__ __forceinline__ void dec8h(const int4 q, float f[8]) {
    float2 a;
    a = __half22float2(*(const __half2*)&q.x); f[0] = a.x; f[1] = a.y;
    a = __half22float2(*(const __half2*)&q.y); f[2] = a.x; f[3] = a.y;
    a = __half22float2(*(const __half2*)&q.z); f[4] = a.x; f[5] = a.y;
    a = __half22float2(*(const __half2*)&q.w); f[6] = a.x; f[7] = a.y;
}

__device__ __forceinline__ int packh2(float a, float b) {
    __half2 h = __floats2half2_rn(a, b);
    return *(const int*)&h;
}

// ---------------------------------------------------------------------------
// Iteration 0 fused with E-precompute: d == 1. Read fp32 X, write E=exp(x)
// as fp16, and do iter-0's row pass (e computed FROM the rounded fp16 so all
// later iterations are self-consistent).
// ---------------------------------------------------------------------------
__global__ void __launch_bounds__(BLK_A, 1)
row_pass_first_kernel(const float* __restrict__ X) {
    __shared__ float s_warp[2][32];

    const int tid  = threadIdx.x;
    const int lane = tid & 31;
    const int wid  = tid >> 5;
    const int b    = blockIdx.x;
    const int row0 = (int)(((long long)N * b)       / GRID_A);
    const int row1 = (int)(((long long)N * (b + 1)) / GRID_A);

    float acc[8];
#pragma unroll
    for (int k = 0; k < 8; k++) acc[k] = 0.0f;

    const float4* x4 = (const float4*)X;
    // preload first row (8 fp32 = 2 float4 per thread)
    float4 xc[2];
    {
        const size_t rb = (size_t)row0 * 2048;
        xc[0] = __ldg(x4 + rb + 2 * tid);
        xc[1] = __ldg(x4 + rb + 2 * tid + 1);
    }

    int buf = 0;
    for (int row = row0; row < row1; ++row, buf ^= 1) {
        // prefetch next row
        float4 xn[2];
        {
            const int nr = (row + 1 < row1) ? row + 1 : row;
            const size_t rb = (size_t)nr * 2048;
            xn[0] = __ldg(x4 + rb + 2 * tid);
            xn[1] = __ldg(x4 + rb + 2 * tid + 1);
        }

        // E = exp(x) -> fp16; e = fp32(E16); row partial sum
        const float* xf = (const float*)xc;
        float E32[8];
#pragma unroll
        for (int k = 0; k < 8; k++) E32[k] = exp2f(xf[k] * LOG2E);

        int4 o;
        o.x = packh2(E32[0], E32[1]);
        o.y = packh2(E32[2], E32[3]);
        o.z = packh2(E32[4], E32[5]);
        o.w = packh2(E32[6], E32[7]);
        g_E[(size_t)row * 1024 + tid] = o;

        float e[8];
        dec8h(o, e);   // rounded values, consistent with later iterations
        float psum = ((e[0] + e[1]) + (e[2] + e[3])) + ((e[4] + e[5]) + (e[6] + e[7]));

        // warp reduce
#pragma unroll
        for (int off = 16; off > 0; off >>= 1)
            psum += __shfl_xor_sync(0xffffffffu, psum, off);
        if (lane == 0) s_warp[buf][wid] = psum;
        __syncthreads();

        float v = s_warp[buf][lane];
#pragma unroll
        for (int off = 16; off > 0; off >>= 1)
            v += __shfl_xor_sync(0xffffffffu, v, off);

        const float rcp = __fdividef(1.0f, v);
        if (tid == 0) g_rinv[row] = rcp;

#pragma unroll
        for (int k = 0; k < 8; k++) acc[k] = fmaf(e[k], rcp, acc[k]);

        xc[0] = xn[0]; xc[1] = xn[1];
    }

    float4* pp = (float4*)(g_part + (size_t)b * N);
    pp[2 * tid]     = make_float4(acc[0], acc[1], acc[2], acc[3]);
    pp[2 * tid + 1] = make_float4(acc[4], acc[5], acc[6], acc[7]);
}

// ---------------------------------------------------------------------------
// Steady-state row pass (iters 1..9): NO transcendentals.
//   e_ij = E_ij * d_j ;  S_i = sum_j e ;  rinv_i = 1/S_i ;  part += e * rinv
// 1024 threads x 8 cols/thread = one int4 (8 fp16) load per thread per row.
// ---------------------------------------------------------------------------
__global__ void __launch_bounds__(BLK_A, 1)
row_pass_kernel() {
    __shared__ float s_warp[2][32];

    const int tid  = threadIdx.x;
    const int lane = tid & 31;
    const int wid  = tid >> 5;
    const int b    = blockIdx.x;
    const int row0 = (int)(((long long)N * b)       / GRID_A);
    const int row1 = (int)(((long long)N * (b + 1)) / GRID_A);

    // column scales d_j for this thread's 8 columns (registers)
    float d[8];
    {
        const float4* d4 = (const float4*)g_d;
        float4 d0 = __ldg(d4 + 2 * tid);
        float4 d1 = __ldg(d4 + 2 * tid + 1);
        d[0]=d0.x; d[1]=d0.y; d[2]=d0.z; d[3]=d0.w;
        d[4]=d1.x; d[5]=d1.y; d[6]=d1.z; d[7]=d1.w;
    }

    float acc[8];
#pragma unroll
    for (int k = 0; k < 8; k++) acc[k] = 0.0f;

    // 2-deep row prefetch (one int4 per thread per row)
    int4 q0 = __ldg(&g_E[(size_t)row0 * 1024 + tid]);
    int4 q1 = __ldg(&g_E[(size_t)min(row0 + 1, row1 - 1) * 1024 + tid]);

    int buf = 0;
    for (int row = row0; row < row1; ++row, buf ^= 1) {
        // prefetch row+2
        const int pr = (row + 2 < row1) ? row + 2 : row1 - 1;
        int4 qn = __ldg(&g_E[(size_t)pr * 1024 + tid]);

        // e = E * d, row partial sum
        float f[8];
        dec8h(q0, f);
        float e[8];
#pragma unroll
        for (int k = 0; k < 8; k++) e[k] = f[k] * d[k];
        float psum = ((e[0] + e[1]) + (e[2] + e[3])) + ((e[4] + e[5]) + (e[6] + e[7]));

        // warp reduce
#pragma unroll
        for (int off = 16; off > 0; off >>= 1)
            psum += __shfl_xor_sync(0xffffffffu, psum, off);
        if (lane == 0) s_warp[buf][wid] = psum;
        __syncthreads();

        // second level: every warp reduces all 32 partials (no 2nd barrier)
        float v = s_warp[buf][lane];
#pragma unroll
        for (int off = 16; off > 0; off >>= 1)
            v += __shfl_xor_sync(0xffffffffu, v, off);

        const float rcp = __fdividef(1.0f, v);
        if (tid == 0) g_rinv[row] = rcp;

#pragma unroll
        for (int k = 0; k < 8; k++) acc[k] = fmaf(e[k], rcp, acc[k]);

        q0 = q1; q1 = qn;
    }

    float4* pp = (float4*)(g_part + (size_t)b * N);
    pp[2 * tid]     = make_float4(acc[0], acc[1], acc[2], acc[3]);
    pp[2 * tid + 1] = make_float4(acc[4], acc[5], acc[6], acc[7]);
}

// ---------------------------------------------------------------------------
// Column reduce: t_j = sum_b part[b][j];  d_j /= t_j   (no logs needed)
// 256 blocks x 256 threads: 32 cols x 8 p-groups, coalesced, 4-way MLP.
// ---------------------------------------------------------------------------
__global__ void __launch_bounds__(256)
col_reduce_kernel() {
    __shared__ float s[8][32];
    const int jl = threadIdx.x & 31;
    const int pg = threadIdx.x >> 5;
    const int j  = blockIdx.x * 32 + jl;

    const int b0 = (GRID_A * pg)       / 8;
    const int b1 = (GRID_A * (pg + 1)) / 8;

    const float* base = g_part + j;
    float a0 = 0.f, a1 = 0.f, a2 = 0.f, a3 = 0.f;
    int u = b0;
    for (; u + 4 <= b1; u += 4) {
        a0 += base[(size_t)(u + 0) * N];
        a1 += base[(size_t)(u + 1) * N];
        a2 += base[(size_t)(u + 2) * N];
        a3 += base[(size_t)(u + 3) * N];
    }
    for (; u < b1; ++u) a0 += base[(size_t)u * N];
    s[pg][jl] = (a0 + a1) + (a2 + a3);
    __syncthreads();

    if (pg == 0) {
        float t = 0.0f;
#pragma unroll
        for (int q = 0; q < 8; q++) t += s[q][jl];
        g_d[j] = __fdividef(g_d[j], t);
    }
}

// ---------------------------------------------------------------------------
// Final: out[i,j] = E_ij * d_j * rinv_i  (pure multiplies)
// ---------------------------------------------------------------------------
__global__ void __launch_bounds__(256)
final_kernel(float* __restrict__ out) {
    const size_t idx = (size_t)blockIdx.x * blockDim.x + threadIdx.x; // int4 idx
    const int    row = (int)(idx >> 10);        // 1024 int4 per row
    const int    cg  = (int)(idx & 1023);

    const float ri = __ldg(g_rinv + row);
    const float4* d4 = (const float4*)g_d;
    float4 d0 = __ldg(d4 + 2 * cg);
    float4 d1 = __ldg(d4 + 2 * cg + 1);

    int4 q = __ldg(&g_E[idx]);
    float f[8];
    dec8h(q, f);

    float4 o0, o1;
    o0.x = f[0] * (d0.x * ri);
    o0.y = f[1] * (d0.y * ri);
    o0.z = f[2] * (d0.z * ri);
    o0.w = f[3] * (d0.w * ri);
    o1.x = f[4] * (d1.x * ri);
    o1.y = f[5] * (d1.y * ri);
    o1.z = f[6] * (d1.z * ri);
    o1.w = f[7] * (d1.w * ri);

    float4* o4 = (float4*)out;
    o4[2 * idx]     = o0;
    o4[2 * idx + 1] = o1;
}

// ---------------------------------------------------------------------------
extern "C" void kernel_launch(void* const* d_in, const int* in_sizes, int n_in,
                              void* d_out, int out_size) {
    const float* X   = (const float*)d_in[0];
    float*       out = (float*)d_out;
    (void)in_sizes; (void)n_in; (void)out_size;

    init_d_kernel<<<N / 256, 256>>>();
    row_pass_first_kernel<<<GRID_A, BLK_A>>>(X);   // iter 0 + E precompute
    col_reduce_kernel<<<N / 32, 256>>>();
    for (int it = 1; it < NITER; ++it) {
        row_pass_kernel<<<GRID_A, BLK_A>>>();
        col_reduce_kernel<<<N / 32, 256>>>();
    }
    final_kernel<<<(size_t)N * N / 8 / 256, 256>>>(out);
}